// round 6
// baseline (speedup 1.0000x reference)
#include <cuda_runtime.h>
#include <cuda_bf16.h>

#define NN 100000
#define NE 1600000
#define NG 512
#define HID 64
#define NCLS 100
#define IDOFF 1500

#define SCAN_BS 1024
#define SCAN_NB ((NN + SCAN_BS - 1) / SCAN_BS)   // 98

// ---------------- device scratch ----------------
__device__ float g_h[NN * HID];        // layer-0 input (embedding gather)
__device__ float g_x[NN * HID];        // (1+eps)*h + agg  (MLP input)
__device__ float g_y[NN * HID];        // MLP output (pre-BN)
__device__ float g_stats[3 * 2 * HID];
__device__ float g_pooled[NG * 3 * HID];
// CSR build (per-launch, graph static within launch)
__device__ int g_deg[NN];
__device__ int g_off[NN + 1];
__device__ int g_cur[NN];
__device__ int g_csr[NE];
__device__ int g_bsum[SCAN_NB];
__device__ int g_boff[SCAN_NB];

// ---------------- helpers ----------------
__device__ __forceinline__ unsigned f2tf(float f) {
    unsigned u;
    asm("cvt.rna.tf32.f32 %0, %1;" : "=r"(u) : "f"(f));
    return u;
}

__device__ __forceinline__ void mma8(float c[4], unsigned a0, unsigned a1,
                                     unsigned a2, unsigned a3,
                                     unsigned b0, unsigned b1) {
    asm volatile(
        "mma.sync.aligned.m16n8k8.row.col.f32.tf32.tf32.f32 "
        "{%0,%1,%2,%3}, {%4,%5,%6,%7}, {%8,%9}, {%0,%1,%2,%3};\n"
        : "+f"(c[0]), "+f"(c[1]), "+f"(c[2]), "+f"(c[3])
        : "r"(a0), "r"(a1), "r"(a2), "r"(a3), "r"(b0), "r"(b1));
}

// ---------------- setup kernels ----------------

__global__ void k_zero() {
    int t = blockIdx.x * blockDim.x + threadIdx.x;
    int stride = gridDim.x * blockDim.x;
    for (int i = t; i < NG * 3 * HID; i += stride) g_pooled[i] = 0.f;
    for (int i = t; i < 3 * 2 * HID; i += stride) g_stats[i] = 0.f;
    for (int i = t; i < NN; i += stride) g_deg[i] = 0;
}

__global__ void k_hist(const int* __restrict__ dst) {
    int e = blockIdx.x * blockDim.x + threadIdx.x;
    if (e < NE) atomicAdd(&g_deg[__ldg(&dst[e])], 1);
}

__global__ void k_scan1() {
    __shared__ int s[SCAN_BS];
    int t = threadIdx.x;
    int i = blockIdx.x * SCAN_BS + t;
    int v = (i < NN) ? g_deg[i] : 0;
    s[t] = v;
    __syncthreads();
    #pragma unroll
    for (int off = 1; off < SCAN_BS; off <<= 1) {
        int u = (t >= off) ? s[t - off] : 0;
        __syncthreads();
        s[t] += u;
        __syncthreads();
    }
    if (i < NN) g_off[i] = s[t] - v;
    if (t == SCAN_BS - 1) g_bsum[blockIdx.x] = s[t];
}

__global__ void k_scan2() {
    __shared__ int s[128];
    int t = threadIdx.x;
    int v = (t < SCAN_NB) ? g_bsum[t] : 0;
    s[t] = v;
    __syncthreads();
    #pragma unroll
    for (int off = 1; off < 128; off <<= 1) {
        int u = (t >= off) ? s[t - off] : 0;
        __syncthreads();
        s[t] += u;
        __syncthreads();
    }
    if (t < SCAN_NB) g_boff[t] = s[t] - v;
    if (t == 127) g_off[NN] = s[127];
}

__global__ void k_scan3() {
    int i = blockIdx.x * SCAN_BS + threadIdx.x;
    if (i >= NN) return;
    int o = g_off[i] + g_boff[blockIdx.x];
    g_off[i] = o;
    g_cur[i] = o;
}

__global__ void k_scatter(const int* __restrict__ src,
                          const int* __restrict__ dst) {
    int e = blockIdx.x * blockDim.x + threadIdx.x;
    if (e >= NE) return;
    int d = __ldg(&dst[e]);
    int pos = atomicAdd(&g_cur[d], 1);
    g_csr[pos] = __ldg(&src[e]);
}

__global__ void k_gather(const int* __restrict__ ids,
                         const float* __restrict__ emb) {
    int t = blockIdx.x * blockDim.x + threadIdx.x;
    if (t >= NN * 16) return;
    int row = t >> 4, q = t & 15;
    int id = ids[row] + IDOFF;
    float4 v = *(const float4*)(emb + (size_t)id * HID + q * 4);
    *(float4*)(g_h + (size_t)row * HID + q * 4) = v;
}

// x[n] = (1+eps[l]) * hbn[n] + sum_nb hbn[s], where hbn = BN_{l-1}(y) for l>0
// (affine hoisted out of the sum: sc*Sum(y) + deg*sh). Warp per node.
__global__ __launch_bounds__(256)
void k_agg(const float* __restrict__ eps,
           const float* __restrict__ gamma,
           const float* __restrict__ beta, int l) {
    int wid = (blockIdx.x * blockDim.x + threadIdx.x) >> 5;
    if (wid >= NN) return;
    int lane = threadIdx.x & 31;
    int c0 = lane * 2;

    // BN coefficients for this lane's two channels (identity for layer 0)
    float sc0 = 1.f, sh0 = 0.f, sc1 = 1.f, sh1 = 0.f;
    const float* HB = g_h;
    if (l > 0) {
        int lp = l - 1;
        const float invN = 1.0f / (float)NN;
        float m0 = __ldg(&g_stats[lp * 128 + c0]) * invN;
        float m1 = __ldg(&g_stats[lp * 128 + c0 + 1]) * invN;
        float v0 = __ldg(&g_stats[lp * 128 + HID + c0]) * invN - m0 * m0;
        float v1 = __ldg(&g_stats[lp * 128 + HID + c0 + 1]) * invN - m1 * m1;
        float i0 = rsqrtf(v0 + 1e-5f);
        float i1 = rsqrtf(v1 + 1e-5f);
        sc0 = __ldg(&gamma[lp * HID + c0]) * i0;
        sc1 = __ldg(&gamma[lp * HID + c0 + 1]) * i1;
        sh0 = __ldg(&beta[lp * HID + c0]) - m0 * sc0;
        sh1 = __ldg(&beta[lp * HID + c0 + 1]) - m1 * sc1;
        HB = g_y;
    }

    int beg = __ldg(&g_off[wid]);
    int end = __ldg(&g_off[wid + 1]);
    float2 a0 = make_float2(0.f, 0.f);
    float2 a1 = make_float2(0.f, 0.f);
    float2 a2 = make_float2(0.f, 0.f);
    float2 a3 = make_float2(0.f, 0.f);
    int j = beg;
    for (; j + 3 < end; j += 4) {
        int s0 = __ldg(&g_csr[j]);
        int s1 = __ldg(&g_csr[j + 1]);
        int s2 = __ldg(&g_csr[j + 2]);
        int s3 = __ldg(&g_csr[j + 3]);
        float2 v0 = __ldg((const float2*)(HB + (size_t)s0 * HID + c0));
        float2 v1 = __ldg((const float2*)(HB + (size_t)s1 * HID + c0));
        float2 v2 = __ldg((const float2*)(HB + (size_t)s2 * HID + c0));
        float2 v3 = __ldg((const float2*)(HB + (size_t)s3 * HID + c0));
        a0.x += v0.x; a0.y += v0.y;
        a1.x += v1.x; a1.y += v1.y;
        a2.x += v2.x; a2.y += v2.y;
        a3.x += v3.x; a3.y += v3.y;
    }
    for (; j < end; j++) {
        int s0 = __ldg(&g_csr[j]);
        float2 v0 = __ldg((const float2*)(HB + (size_t)s0 * HID + c0));
        a0.x += v0.x; a0.y += v0.y;
    }
    float sumx = (a0.x + a1.x) + (a2.x + a3.x);
    float sumy = (a0.y + a1.y) + (a2.y + a3.y);
    float deg = (float)(end - beg);
    float se = 1.0f + __ldg(&eps[l]);
    float2 yv = *(const float2*)(HB + (size_t)wid * HID + c0);
    float h0 = yv.x * sc0 + sh0;
    float h1 = yv.y * sc1 + sh1;
    float2 o = make_float2(se * h0 + sc0 * sumx + deg * sh0,
                           se * h1 + sc1 * sumy + deg * sh1);
    *(float2*)(g_x + (size_t)wid * HID + c0) = o;
}

// Fused 3x (Linear 64x64 + ReLU), 3xTF32 split mma, BN stats.
// W packed interleaved (hi,lo) pairs, row stride 136 words -> conflict-free
// LDS.64 B-fragment loads (bank-pair = 4*tg + g bijection per phase).
#define MROWS 128
#define XS 76
#define KSTR 136
#define MLP_SMEM ((MROWS * XS + HID * KSTR + HID + 2 * HID) * 4)

__global__ __launch_bounds__(256, 2)
void k_mlp(const float* __restrict__ Wall, const float* __restrict__ ball, int l) {
    extern __shared__ float sm[];
    float* Xbuf = sm;
    unsigned* Wp = (unsigned*)(sm + MROWS * XS);
    float* Bsm = (float*)(Wp + HID * KSTR);
    float* bstat = Bsm + HID;

    const int t = threadIdx.x;
    const int warp = t >> 5, lane = t & 31;
    const int g = lane >> 2, tg = lane & 3;
    const int row0 = blockIdx.x * MROWS;
    const int wrow = warp * 16;

    if (t < 2 * HID) bstat[t] = 0.f;

    for (int i = t; i < MROWS * 16; i += 256) {
        int r = i >> 4, q = i & 15;
        float4 v = make_float4(0.f, 0.f, 0.f, 0.f);
        int gr = row0 + r;
        if (gr < NN) v = *(const float4*)(g_x + (size_t)gr * HID + q * 4);
        float* p = Xbuf + r * XS + q * 4;
        p[0] = v.x; p[1] = v.y; p[2] = v.z; p[3] = v.w;
    }

    for (int m = 0; m < 3; m++) {
        __syncthreads();
        const float* W = Wall + (size_t)(l * 3 + m) * HID * HID;
        for (int i = t; i < HID * 16; i += 256) {
            int k = i >> 4, q = i & 15;
            float4 w = *(const float4*)(W + (size_t)k * HID + q * 4);
            unsigned h0 = f2tf(w.x), h1 = f2tf(w.y), h2 = f2tf(w.z), h3 = f2tf(w.w);
            uint2* pp = (uint2*)(Wp + k * KSTR + q * 8);
            pp[0] = make_uint2(h0, f2tf(w.x - __uint_as_float(h0)));
            pp[1] = make_uint2(h1, f2tf(w.y - __uint_as_float(h1)));
            pp[2] = make_uint2(h2, f2tf(w.z - __uint_as_float(h2)));
            pp[3] = make_uint2(h3, f2tf(w.w - __uint_as_float(h3)));
        }
        if (t < HID) Bsm[t] = ball[(l * 3 + m) * HID + t];
        __syncthreads();

        float acc[8][4];
        #pragma unroll
        for (int n = 0; n < 8; n++) {
            acc[n][0] = 0.f; acc[n][1] = 0.f; acc[n][2] = 0.f; acc[n][3] = 0.f;
        }

        #pragma unroll
        for (int k0 = 0; k0 < 8; k0++) {
            int kk = k0 * 8;
            float a0f = Xbuf[(wrow + g) * XS + kk + tg];
            float a1f = Xbuf[(wrow + g + 8) * XS + kk + tg];
            float a2f = Xbuf[(wrow + g) * XS + kk + tg + 4];
            float a3f = Xbuf[(wrow + g + 8) * XS + kk + tg + 4];
            unsigned a0h = f2tf(a0f), a1h = f2tf(a1f);
            unsigned a2h = f2tf(a2f), a3h = f2tf(a3f);
            unsigned a0l = f2tf(a0f - __uint_as_float(a0h));
            unsigned a1l = f2tf(a1f - __uint_as_float(a1h));
            unsigned a2l = f2tf(a2f - __uint_as_float(a2h));
            unsigned a3l = f2tf(a3f - __uint_as_float(a3h));
            #pragma unroll
            for (int n = 0; n < 8; n++) {
                uint2 b0 = *(const uint2*)(Wp + (kk + tg) * KSTR + (n * 8 + g) * 2);
                uint2 b1 = *(const uint2*)(Wp + (kk + tg + 4) * KSTR + (n * 8 + g) * 2);
                mma8(acc[n], a0h, a1h, a2h, a3h, b0.y, b1.y);  // Ahi*Blo
                mma8(acc[n], a0l, a1l, a2l, a3l, b0.x, b1.x);  // Alo*Bhi
                mma8(acc[n], a0h, a1h, a2h, a3h, b0.x, b1.x);  // Ahi*Bhi
            }
        }

        if (m < 2) {
            #pragma unroll
            for (int n = 0; n < 8; n++) {
                int c = n * 8 + 2 * tg;
                float b0f = Bsm[c], b1f = Bsm[c + 1];
                float d0 = fmaxf(acc[n][0] + b0f, 0.f);
                float d1 = fmaxf(acc[n][1] + b1f, 0.f);
                float d2 = fmaxf(acc[n][2] + b0f, 0.f);
                float d3 = fmaxf(acc[n][3] + b1f, 0.f);
                float* p0 = Xbuf + (wrow + g) * XS + c;
                p0[0] = d0; p0[1] = d1;
                float* p1 = Xbuf + (wrow + g + 8) * XS + c;
                p1[0] = d2; p1[1] = d3;
            }
            __syncwarp();
        } else {
            int r0v = row0 + wrow + g;
            int r1v = r0v + 8;
            bool v0 = r0v < NN, v1 = r1v < NN;
            #pragma unroll
            for (int n = 0; n < 8; n++) {
                int c = n * 8 + 2 * tg;
                float b0f = Bsm[c], b1f = Bsm[c + 1];
                float d0 = fmaxf(acc[n][0] + b0f, 0.f);
                float d1 = fmaxf(acc[n][1] + b1f, 0.f);
                float d2 = fmaxf(acc[n][2] + b0f, 0.f);
                float d3 = fmaxf(acc[n][3] + b1f, 0.f);
                if (v0) *(float2*)(g_y + (size_t)r0v * HID + c) = make_float2(d0, d1);
                if (v1) *(float2*)(g_y + (size_t)r1v * HID + c) = make_float2(d2, d3);
                float s0 = (v0 ? d0 : 0.f) + (v1 ? d2 : 0.f);
                float s1 = (v0 ? d1 : 0.f) + (v1 ? d3 : 0.f);
                float q0 = (v0 ? d0 * d0 : 0.f) + (v1 ? d2 * d2 : 0.f);
                float q1 = (v0 ? d1 * d1 : 0.f) + (v1 ? d3 * d3 : 0.f);
                #pragma unroll
                for (int off = 4; off < 32; off <<= 1) {
                    s0 += __shfl_xor_sync(0xffffffffu, s0, off);
                    s1 += __shfl_xor_sync(0xffffffffu, s1, off);
                    q0 += __shfl_xor_sync(0xffffffffu, q0, off);
                    q1 += __shfl_xor_sync(0xffffffffu, q1, off);
                }
                if (g == 0) {
                    atomicAdd(&bstat[c], s0);
                    atomicAdd(&bstat[c + 1], s1);
                    atomicAdd(&bstat[HID + c], q0);
                    atomicAdd(&bstat[HID + c + 1], q1);
                }
            }
        }
    }
    __syncthreads();
    if (t < 2 * HID) atomicAdd(&g_stats[l * 2 * HID + t], bstat[t]);
}

// BN apply (read-only) + per-graph pooling. No g_h writeback.
__global__ void k_pool(const int* __restrict__ graph_ids,
                       const float* __restrict__ gamma,
                       const float* __restrict__ beta, int l) {
    __shared__ int gid[256];
    int t = threadIdx.x;
    int c = t & 63, sub = t >> 6;
    int base = blockIdx.x * 256;
    int nrow_blk = NN - base; if (nrow_blk > 256) nrow_blk = 256;
    if (t < nrow_blk) gid[t] = graph_ids[base + t];
    __syncthreads();

    float sum = g_stats[l * 2 * HID + c];
    float sq = g_stats[l * 2 * HID + HID + c];
    const float invN = 1.0f / (float)NN;
    float mean = sum * invN;
    float var = sq * invN - mean * mean;
    float inv = rsqrtf(var + 1e-5f);
    float sc = __ldg(&gamma[l * HID + c]) * inv;
    float sh = __ldg(&beta[l * HID + c]) - mean * sc;

    int r0 = sub * 64;
    int nr = nrow_blk - r0; if (nr > 64) nr = 64;
    if (nr <= 0) return;

    float run = 0.f;
    int gcur = gid[r0];
    for (int r = 0; r < nr; r++) {
        int gg = gid[r0 + r];
        if (gg != gcur) {
            atomicAdd(&g_pooled[(size_t)gcur * (3 * HID) + l * HID + c], run);
            run = 0.f;
            gcur = gg;
        }
        run += g_y[(size_t)(base + r0 + r) * HID + c] * sc + sh;
    }
    atomicAdd(&g_pooled[(size_t)gcur * (3 * HID) + l * HID + c], run);
}

// out[g] = pooled[g] @ W_out + b_out
__global__ void k_out(const float* __restrict__ Wo,
                      const float* __restrict__ bo,
                      float* __restrict__ out) {
    __shared__ float p[3 * HID];
    int gr = blockIdx.x;
    int t = threadIdx.x;
    for (int i = t; i < 3 * HID; i += blockDim.x)
        p[i] = g_pooled[(size_t)gr * (3 * HID) + i];
    __syncthreads();
    if (t < NCLS) {
        float a = __ldg(&bo[t]);
        #pragma unroll 8
        for (int k = 0; k < 3 * HID; k++) a += p[k] * Wo[(size_t)k * NCLS + t];
        out[(size_t)gr * NCLS + t] = a;
    }
}

// ---------------- launch ----------------
extern "C" void kernel_launch(void* const* d_in, const int* in_sizes, int n_in,
                              void* d_out, int out_size) {
    const int* node_ids = (const int*)d_in[0];
    const int* edge_src = (const int*)d_in[1];
    const int* edge_dst = (const int*)d_in[2];
    const int* graph_ids = (const int*)d_in[3];
    const float* emb = (const float*)d_in[4];
    const float* Ws = (const float*)d_in[5];
    const float* bs = (const float*)d_in[6];
    const float* gamma = (const float*)d_in[7];
    const float* beta = (const float*)d_in[8];
    const float* eps = (const float*)d_in[9];
    const float* Wo = (const float*)d_in[10];
    const float* bo = (const float*)d_in[11];
    float* out = (float*)d_out;

    cudaFuncSetAttribute(k_mlp, cudaFuncAttributeMaxDynamicSharedMemorySize,
                         MLP_SMEM);

    k_zero<<<256, 256>>>();
    k_hist<<<(NE + 255) / 256, 256>>>(edge_dst);
    k_gather<<<(NN * 16 + 255) / 256, 256>>>(node_ids, emb);
    k_scan1<<<SCAN_NB, SCAN_BS>>>();
    k_scan2<<<1, 128>>>();
    k_scan3<<<SCAN_NB, SCAN_BS>>>();
    k_scatter<<<(NE + 255) / 256, 256>>>(edge_src, edge_dst);

    for (int l = 0; l < 3; l++) {
        k_agg<<<(NN * 32 + 255) / 256, 256>>>(eps, gamma, beta, l);
        k_mlp<<<(NN + MROWS - 1) / MROWS, 256, MLP_SMEM>>>(Ws, bs, l);
        k_pool<<<(NN + 255) / 256, 256>>>(graph_ids, gamma, beta, l);
    }

    k_out<<<NG, 128>>>(Wo, bo, out);
}

// round 9
// speedup vs baseline: 1.0095x; 1.0095x over previous
#include <cuda_runtime.h>
#include <cuda_bf16.h>

#define NN 100000
#define NE 1600000
#define NG 512
#define HID 64
#define NCLS 100
#define IDOFF 1500

#define SCAN_BS 1024
#define SCAN_NB ((NN + SCAN_BS - 1) / SCAN_BS)   // 98

// ---------------- device scratch ----------------
__device__ float g_h[NN * HID];        // layer-0 input (embedding gather)
__device__ float g_x[NN * HID];        // (1+eps)*h + agg  (MLP input)
__device__ float g_y[NN * HID];        // MLP output (pre-BN)
__device__ float g_stats[3 * 2 * HID];
__device__ float g_pooled[NG * 3 * HID];
// CSR build (per-launch, graph static within launch)
__device__ int g_deg[NN];
__device__ int g_off[NN + 1];
__device__ int g_cur[NN];
__device__ int g_csr[NE];
__device__ int g_bsum[SCAN_NB];
__device__ int g_boff[SCAN_NB];

// ---------------- helpers ----------------
__device__ __forceinline__ unsigned f2tf(float f) {
    unsigned u;
    asm("cvt.rna.tf32.f32 %0, %1;" : "=r"(u) : "f"(f));
    return u;
}

__device__ __forceinline__ void mma8(float c[4], unsigned a0, unsigned a1,
                                     unsigned a2, unsigned a3,
                                     unsigned b0, unsigned b1) {
    asm volatile(
        "mma.sync.aligned.m16n8k8.row.col.f32.tf32.tf32.f32 "
        "{%0,%1,%2,%3}, {%4,%5,%6,%7}, {%8,%9}, {%0,%1,%2,%3};\n"
        : "+f"(c[0]), "+f"(c[1]), "+f"(c[2]), "+f"(c[3])
        : "r"(a0), "r"(a1), "r"(a2), "r"(a3), "r"(b0), "r"(b1));
}

// ---------------- setup kernels ----------------

__global__ void k_zero() {
    int t = blockIdx.x * blockDim.x + threadIdx.x;
    int stride = gridDim.x * blockDim.x;
    for (int i = t; i < NG * 3 * HID; i += stride) g_pooled[i] = 0.f;
    for (int i = t; i < 3 * 2 * HID; i += stride) g_stats[i] = 0.f;
    for (int i = t; i < NN; i += stride) g_deg[i] = 0;
}

__global__ void k_hist(const int* __restrict__ dst) {
    int e = blockIdx.x * blockDim.x + threadIdx.x;
    if (e < NE) atomicAdd(&g_deg[__ldg(&dst[e])], 1);
}

__global__ void k_scan1() {
    __shared__ int s[SCAN_BS];
    int t = threadIdx.x;
    int i = blockIdx.x * SCAN_BS + t;
    int v = (i < NN) ? g_deg[i] : 0;
    s[t] = v;
    __syncthreads();
    #pragma unroll
    for (int off = 1; off < SCAN_BS; off <<= 1) {
        int u = (t >= off) ? s[t - off] : 0;
        __syncthreads();
        s[t] += u;
        __syncthreads();
    }
    if (i < NN) g_off[i] = s[t] - v;
    if (t == SCAN_BS - 1) g_bsum[blockIdx.x] = s[t];
}

__global__ void k_scan2() {
    __shared__ int s[128];
    int t = threadIdx.x;
    int v = (t < SCAN_NB) ? g_bsum[t] : 0;
    s[t] = v;
    __syncthreads();
    #pragma unroll
    for (int off = 1; off < 128; off <<= 1) {
        int u = (t >= off) ? s[t - off] : 0;
        __syncthreads();
        s[t] += u;
        __syncthreads();
    }
    if (t < SCAN_NB) g_boff[t] = s[t] - v;
    if (t == 127) g_off[NN] = s[127];
}

__global__ void k_scan3() {
    int i = blockIdx.x * SCAN_BS + threadIdx.x;
    if (i >= NN) return;
    int o = g_off[i] + g_boff[blockIdx.x];
    g_off[i] = o;
    g_cur[i] = o;
}

__global__ void k_scatter(const int* __restrict__ src,
                          const int* __restrict__ dst) {
    int e = blockIdx.x * blockDim.x + threadIdx.x;
    if (e >= NE) return;
    int d = __ldg(&dst[e]);
    int pos = atomicAdd(&g_cur[d], 1);
    g_csr[pos] = __ldg(&src[e]);
}

__global__ void k_gather(const int* __restrict__ ids,
                         const float* __restrict__ emb) {
    int t = blockIdx.x * blockDim.x + threadIdx.x;
    if (t >= NN * 16) return;
    int row = t >> 4, q = t & 15;
    int id = ids[row] + IDOFF;
    float4 v = *(const float4*)(emb + (size_t)id * HID + q * 4);
    *(float4*)(g_h + (size_t)row * HID + q * 4) = v;
}

// x[n] = (1+eps[l]) * hbn[n] + sum_nb hbn[s], where hbn = BN_{l-1}(y) for l>0
// (affine hoisted out of the sum: sc*Sum(y) + deg*sh). Warp per node.
__global__ __launch_bounds__(256)
void k_agg(const float* __restrict__ eps,
           const float* __restrict__ gamma,
           const float* __restrict__ beta, int l) {
    int wid = (blockIdx.x * blockDim.x + threadIdx.x) >> 5;
    if (wid >= NN) return;
    int lane = threadIdx.x & 31;
    int c0 = lane * 2;

    float sc0 = 1.f, sh0 = 0.f, sc1 = 1.f, sh1 = 0.f;
    const float* HB = g_h;
    if (l > 0) {
        int lp = l - 1;
        const float invN = 1.0f / (float)NN;
        float m0 = __ldg(&g_stats[lp * 128 + c0]) * invN;
        float m1 = __ldg(&g_stats[lp * 128 + c0 + 1]) * invN;
        float v0 = __ldg(&g_stats[lp * 128 + HID + c0]) * invN - m0 * m0;
        float v1 = __ldg(&g_stats[lp * 128 + HID + c0 + 1]) * invN - m1 * m1;
        float i0 = rsqrtf(v0 + 1e-5f);
        float i1 = rsqrtf(v1 + 1e-5f);
        sc0 = __ldg(&gamma[lp * HID + c0]) * i0;
        sc1 = __ldg(&gamma[lp * HID + c0 + 1]) * i1;
        sh0 = __ldg(&beta[lp * HID + c0]) - m0 * sc0;
        sh1 = __ldg(&beta[lp * HID + c0 + 1]) - m1 * sc1;
        HB = g_y;
    }

    int beg = __ldg(&g_off[wid]);
    int end = __ldg(&g_off[wid + 1]);
    float2 a0 = make_float2(0.f, 0.f);
    float2 a1 = make_float2(0.f, 0.f);
    float2 a2 = make_float2(0.f, 0.f);
    float2 a3 = make_float2(0.f, 0.f);
    int j = beg;
    for (; j + 3 < end; j += 4) {
        int s0 = __ldg(&g_csr[j]);
        int s1 = __ldg(&g_csr[j + 1]);
        int s2 = __ldg(&g_csr[j + 2]);
        int s3 = __ldg(&g_csr[j + 3]);
        float2 v0 = __ldg((const float2*)(HB + (size_t)s0 * HID + c0));
        float2 v1 = __ldg((const float2*)(HB + (size_t)s1 * HID + c0));
        float2 v2 = __ldg((const float2*)(HB + (size_t)s2 * HID + c0));
        float2 v3 = __ldg((const float2*)(HB + (size_t)s3 * HID + c0));
        a0.x += v0.x; a0.y += v0.y;
        a1.x += v1.x; a1.y += v1.y;
        a2.x += v2.x; a2.y += v2.y;
        a3.x += v3.x; a3.y += v3.y;
    }
    for (; j < end; j++) {
        int s0 = __ldg(&g_csr[j]);
        float2 v0 = __ldg((const float2*)(HB + (size_t)s0 * HID + c0));
        a0.x += v0.x; a0.y += v0.y;
    }
    float sumx = (a0.x + a1.x) + (a2.x + a3.x);
    float sumy = (a0.y + a1.y) + (a2.y + a3.y);
    float deg = (float)(end - beg);
    float se = 1.0f + __ldg(&eps[l]);
    float2 yv = *(const float2*)(HB + (size_t)wid * HID + c0);
    float h0 = yv.x * sc0 + sh0;
    float h1 = yv.y * sc1 + sh1;
    float2 o = make_float2(se * h0 + sc0 * sumx + deg * sh0,
                           se * h1 + sc1 * sumy + deg * sh1);
    *(float2*)(g_x + (size_t)wid * HID + c0) = o;
}

// Fused 3x (Linear 64x64 + ReLU), 3xTF32 split mma, BN stats.
// Separate Whi/Wlo tiles, stride 72 words: bank = 8*tg + g (bijection) ->
// conflict-free B-fragment LDS.
#define MROWS 128
#define XS 76
#define WSTR 72
#define MLP_SMEM ((MROWS * XS + 2 * HID * WSTR + HID + 2 * HID) * 4)

__global__ __launch_bounds__(256, 2)
void k_mlp(const float* __restrict__ Wall, const float* __restrict__ ball, int l) {
    extern __shared__ float sm[];
    float* Xbuf = sm;
    unsigned* Whi = (unsigned*)(sm + MROWS * XS);
    unsigned* Wlo = Whi + HID * WSTR;
    float* Bsm = (float*)(Wlo + HID * WSTR);
    float* bstat = Bsm + HID;

    const int t = threadIdx.x;
    const int warp = t >> 5, lane = t & 31;
    const int g = lane >> 2, tg = lane & 3;
    const int row0 = blockIdx.x * MROWS;
    const int wrow = warp * 16;

    if (t < 2 * HID) bstat[t] = 0.f;

    for (int i = t; i < MROWS * 16; i += 256) {
        int r = i >> 4, q = i & 15;
        float4 v = make_float4(0.f, 0.f, 0.f, 0.f);
        int gr = row0 + r;
        if (gr < NN) v = *(const float4*)(g_x + (size_t)gr * HID + q * 4);
        float* p = Xbuf + r * XS + q * 4;
        p[0] = v.x; p[1] = v.y; p[2] = v.z; p[3] = v.w;
    }

    for (int m = 0; m < 3; m++) {
        __syncthreads();
        const float* W = Wall + (size_t)(l * 3 + m) * HID * HID;
        for (int i = t; i < HID * 16; i += 256) {
            int k = i >> 4, q = i & 15;
            float4 w = *(const float4*)(W + (size_t)k * HID + q * 4);
            unsigned h0 = f2tf(w.x), h1 = f2tf(w.y), h2 = f2tf(w.z), h3 = f2tf(w.w);
            unsigned* ph = Whi + k * WSTR + q * 4;
            ph[0] = h0; ph[1] = h1; ph[2] = h2; ph[3] = h3;
            unsigned* pl = Wlo + k * WSTR + q * 4;
            pl[0] = f2tf(w.x - __uint_as_float(h0));
            pl[1] = f2tf(w.y - __uint_as_float(h1));
            pl[2] = f2tf(w.z - __uint_as_float(h2));
            pl[3] = f2tf(w.w - __uint_as_float(h3));
        }
        if (t < HID) Bsm[t] = ball[(l * 3 + m) * HID + t];
        __syncthreads();

        float acc[8][4];
        #pragma unroll
        for (int n = 0; n < 8; n++) {
            acc[n][0] = 0.f; acc[n][1] = 0.f; acc[n][2] = 0.f; acc[n][3] = 0.f;
        }

        #pragma unroll
        for (int k0 = 0; k0 < 8; k0++) {
            int kk = k0 * 8;
            float a0f = Xbuf[(wrow + g) * XS + kk + tg];
            float a1f = Xbuf[(wrow + g + 8) * XS + kk + tg];
            float a2f = Xbuf[(wrow + g) * XS + kk + tg + 4];
            float a3f = Xbuf[(wrow + g + 8) * XS + kk + tg + 4];
            unsigned a0h = f2tf(a0f), a1h = f2tf(a1f);
            unsigned a2h = f2tf(a2f), a3h = f2tf(a3f);
            unsigned a0l = f2tf(a0f - __uint_as_float(a0h));
            unsigned a1l = f2tf(a1f - __uint_as_float(a1h));
            unsigned a2l = f2tf(a2f - __uint_as_float(a2h));
            unsigned a3l = f2tf(a3f - __uint_as_float(a3h));
            #pragma unroll
            for (int n = 0; n < 8; n++) {
                unsigned b0h = Whi[(kk + tg) * WSTR + n * 8 + g];
                unsigned b1h = Whi[(kk + tg + 4) * WSTR + n * 8 + g];
                unsigned b0l = Wlo[(kk + tg) * WSTR + n * 8 + g];
                unsigned b1l = Wlo[(kk + tg + 4) * WSTR + n * 8 + g];
                mma8(acc[n], a0h, a1h, a2h, a3h, b0l, b1l);
                mma8(acc[n], a0l, a1l, a2l, a3l, b0h, b1h);
                mma8(acc[n], a0h, a1h, a2h, a3h, b0h, b1h);
            }
        }

        if (m < 2) {
            #pragma unroll
            for (int n = 0; n < 8; n++) {
                int c = n * 8 + 2 * tg;
                float b0f = Bsm[c], b1f = Bsm[c + 1];
                float d0 = fmaxf(acc[n][0] + b0f, 0.f);
                float d1 = fmaxf(acc[n][1] + b1f, 0.f);
                float d2 = fmaxf(acc[n][2] + b0f, 0.f);
                float d3 = fmaxf(acc[n][3] + b1f, 0.f);
                float* p0 = Xbuf + (wrow + g) * XS + c;
                p0[0] = d0; p0[1] = d1;
                float* p1 = Xbuf + (wrow + g + 8) * XS + c;
                p1[0] = d2; p1[1] = d3;
            }
            __syncwarp();
        } else {
            int r0v = row0 + wrow + g;
            int r1v = r0v + 8;
            bool v0 = r0v < NN, v1 = r1v < NN;
            #pragma unroll
            for (int n = 0; n < 8; n++) {
                int c = n * 8 + 2 * tg;
                float b0f = Bsm[c], b1f = Bsm[c + 1];
                float d0 = fmaxf(acc[n][0] + b0f, 0.f);
                float d1 = fmaxf(acc[n][1] + b1f, 0.f);
                float d2 = fmaxf(acc[n][2] + b0f, 0.f);
                float d3 = fmaxf(acc[n][3] + b1f, 0.f);
                if (v0) *(float2*)(g_y + (size_t)r0v * HID + c) = make_float2(d0, d1);
                if (v1) *(float2*)(g_y + (size_t)r1v * HID + c) = make_float2(d2, d3);
                float s0 = (v0 ? d0 : 0.f) + (v1 ? d2 : 0.f);
                float s1 = (v0 ? d1 : 0.f) + (v1 ? d3 : 0.f);
                float q0 = (v0 ? d0 * d0 : 0.f) + (v1 ? d2 * d2 : 0.f);
                float q1 = (v0 ? d1 * d1 : 0.f) + (v1 ? d3 * d3 : 0.f);
                #pragma unroll
                for (int off = 4; off < 32; off <<= 1) {
                    s0 += __shfl_xor_sync(0xffffffffu, s0, off);
                    s1 += __shfl_xor_sync(0xffffffffu, s1, off);
                    q0 += __shfl_xor_sync(0xffffffffu, q0, off);
                    q1 += __shfl_xor_sync(0xffffffffu, q1, off);
                }
                if (g == 0) {
                    atomicAdd(&bstat[c], s0);
                    atomicAdd(&bstat[c + 1], s1);
                    atomicAdd(&bstat[HID + c], q0);
                    atomicAdd(&bstat[HID + c + 1], q1);
                }
            }
        }
    }
    __syncthreads();
    if (t < 2 * HID) atomicAdd(&g_stats[l * 2 * HID + t], bstat[t]);
}

// BN apply (read-only) + per-graph pooling. No g_h writeback.
__global__ void k_pool(const int* __restrict__ graph_ids,
                       const float* __restrict__ gamma,
                       const float* __restrict__ beta, int l) {
    __shared__ int gid[256];
    int t = threadIdx.x;
    int c = t & 63, sub = t >> 6;
    int base = blockIdx.x * 256;
    int nrow_blk = NN - base; if (nrow_blk > 256) nrow_blk = 256;
    if (t < nrow_blk) gid[t] = graph_ids[base + t];
    __syncthreads();

    float sum = g_stats[l * 2 * HID + c];
    float sq = g_stats[l * 2 * HID + HID + c];
    const float invN = 1.0f / (float)NN;
    float mean = sum * invN;
    float var = sq * invN - mean * mean;
    float inv = rsqrtf(var + 1e-5f);
    float sc = __ldg(&gamma[l * HID + c]) * inv;
    float sh = __ldg(&beta[l * HID + c]) - mean * sc;

    int r0 = sub * 64;
    int nr = nrow_blk - r0; if (nr > 64) nr = 64;
    if (nr <= 0) return;

    float run = 0.f;
    int gcur = gid[r0];
    for (int r = 0; r < nr; r++) {
        int gg = gid[r0 + r];
        if (gg != gcur) {
            atomicAdd(&g_pooled[(size_t)gcur * (3 * HID) + l * HID + c], run);
            run = 0.f;
            gcur = gg;
        }
        run += g_y[(size_t)(base + r0 + r) * HID + c] * sc + sh;
    }
    atomicAdd(&g_pooled[(size_t)gcur * (3 * HID) + l * HID + c], run);
}

// out[g] = pooled[g] @ W_out + b_out
__global__ void k_out(const float* __restrict__ Wo,
                      const float* __restrict__ bo,
                      float* __restrict__ out) {
    __shared__ float p[3 * HID];
    int gr = blockIdx.x;
    int t = threadIdx.x;
    for (int i = t; i < 3 * HID; i += blockDim.x)
        p[i] = g_pooled[(size_t)gr * (3 * HID) + i];
    __syncthreads();
    if (t < NCLS) {
        float a = __ldg(&bo[t]);
        #pragma unroll 8
        for (int k = 0; k < 3 * HID; k++) a += p[k] * Wo[(size_t)k * NCLS + t];
        out[(size_t)gr * NCLS + t] = a;
    }
}

// ---------------- launch ----------------
extern "C" void kernel_launch(void* const* d_in, const int* in_sizes, int n_in,
                              void* d_out, int out_size) {
    const int* node_ids = (const int*)d_in[0];
    const int* edge_src = (const int*)d_in[1];
    const int* edge_dst = (const int*)d_in[2];
    const int* graph_ids = (const int*)d_in[3];
    const float* emb = (const float*)d_in[4];
    const float* Ws = (const float*)d_in[5];
    const float* bs = (const float*)d_in[6];
    const float* gamma = (const float*)d_in[7];
    const float* beta = (const float*)d_in[8];
    const float* eps = (const float*)d_in[9];
    const float* Wo = (const float*)d_in[10];
    const float* bo = (const float*)d_in[11];
    float* out = (float*)d_out;

    cudaFuncSetAttribute(k_mlp, cudaFuncAttributeMaxDynamicSharedMemorySize,
                         MLP_SMEM);

    k_zero<<<256, 256>>>();
    k_hist<<<(NE + 255) / 256, 256>>>(edge_dst);
    k_gather<<<(NN * 16 + 255) / 256, 256>>>(node_ids, emb);
    k_scan1<<<SCAN_NB, SCAN_BS>>>();
    k_scan2<<<1, 128>>>();
    k_scan3<<<SCAN_NB, SCAN_BS>>>();
    k_scatter<<<(NE + 255) / 256, 256>>>(edge_src, edge_dst);

    for (int l = 0; l < 3; l++) {
        k_agg<<<(NN * 32 + 255) / 256, 256>>>(eps, gamma, beta, l);
        k_mlp<<<(NN + MROWS - 1) / MROWS, 256, MLP_SMEM>>>(Ws, bs, l);
        k_pool<<<(NN + 255) / 256, 256>>>(graph_ids, gamma, beta, l);
    }

    k_out<<<NG, 128>>>(Wo, bo, out);
}

// round 11
// speedup vs baseline: 1.2927x; 1.2806x over previous
#include <cuda_runtime.h>
#include <cuda_bf16.h>

#define NN 100000
#define NE 1600000
#define NG 512
#define HID 64
#define NCLS 100
#define IDOFF 1500

#define SCAN_BS 1024
#define SCAN_NB ((NN + SCAN_BS - 1) / SCAN_BS)   // 98

// ---------------- device scratch ----------------
__device__ float g_h[NN * HID];        // layer input h (post-BN)
__device__ float g_x[NN * HID];        // (1+eps)*h + agg  (MLP input)
__device__ float g_y[NN * HID];        // MLP output (pre-BN)
__device__ float g_stats[3 * 2 * HID];
__device__ float g_pooled[NG * 3 * HID];
__device__ unsigned g_whi2[9 * 2048];  // packed bf16 hi pairs [stage][kpair][n]
__device__ unsigned g_wlo2[9 * 2048];  // packed bf16 lo pairs
// CSR build (per-launch, graph static within launch)
__device__ int g_deg[NN];
__device__ int g_off[NN + 1];
__device__ int g_cur[NN];
__device__ int g_csr[NE];
__device__ int g_bsum[SCAN_NB];
__device__ int g_boff[SCAN_NB];

// ---------------- helpers ----------------
__device__ __forceinline__ void mma16(float c[4], unsigned a0, unsigned a1,
                                      unsigned a2, unsigned a3,
                                      unsigned b0, unsigned b1) {
    asm volatile(
        "mma.sync.aligned.m16n8k16.row.col.f32.bf16.bf16.f32 "
        "{%0,%1,%2,%3}, {%4,%5,%6,%7}, {%8,%9}, {%0,%1,%2,%3};\n"
        : "+f"(c[0]), "+f"(c[1]), "+f"(c[2]), "+f"(c[3])
        : "r"(a0), "r"(a1), "r"(a2), "r"(a3), "r"(b0), "r"(b1));
}

__device__ __forceinline__ unsigned pack_bf2(__nv_bfloat16 x, __nv_bfloat16 y) {
    return (unsigned)__bfloat16_as_ushort(x) |
           ((unsigned)__bfloat16_as_ushort(y) << 16);
}

// split float2 into bf16-hi packed word + bf16-lo packed word
__device__ __forceinline__ void bfsplit2(float2 v, unsigned& hi, unsigned& lo) {
    __nv_bfloat16 hx = __float2bfloat16_rn(v.x);
    __nv_bfloat16 hy = __float2bfloat16_rn(v.y);
    __nv_bfloat16 lx = __float2bfloat16_rn(v.x - __bfloat162float(hx));
    __nv_bfloat16 ly = __float2bfloat16_rn(v.y - __bfloat162float(hy));
    hi = pack_bf2(hx, hy);
    lo = pack_bf2(lx, ly);
}

// ---------------- setup kernels ----------------

__global__ void k_zero() {
    int t = blockIdx.x * blockDim.x + threadIdx.x;
    int stride = gridDim.x * blockDim.x;
    for (int i = t; i < NG * 3 * HID; i += stride) g_pooled[i] = 0.f;
    for (int i = t; i < 3 * 2 * HID; i += stride) g_stats[i] = 0.f;
    for (int i = t; i < NN; i += stride) g_deg[i] = 0;
}

__global__ void k_hist(const int* __restrict__ dst) {
    int e = blockIdx.x * blockDim.x + threadIdx.x;
    if (e < NE) atomicAdd(&g_deg[__ldg(&dst[e])], 1);
}

__global__ void k_scan1() {
    __shared__ int s[SCAN_BS];
    int t = threadIdx.x;
    int i = blockIdx.x * SCAN_BS + t;
    int v = (i < NN) ? g_deg[i] : 0;
    s[t] = v;
    __syncthreads();
    #pragma unroll
    for (int off = 1; off < SCAN_BS; off <<= 1) {
        int u = (t >= off) ? s[t - off] : 0;
        __syncthreads();
        s[t] += u;
        __syncthreads();
    }
    if (i < NN) g_off[i] = s[t] - v;
    if (t == SCAN_BS - 1) g_bsum[blockIdx.x] = s[t];
}

__global__ void k_scan2() {
    __shared__ int s[128];
    int t = threadIdx.x;
    int v = (t < SCAN_NB) ? g_bsum[t] : 0;
    s[t] = v;
    __syncthreads();
    #pragma unroll
    for (int off = 1; off < 128; off <<= 1) {
        int u = (t >= off) ? s[t - off] : 0;
        __syncthreads();
        s[t] += u;
        __syncthreads();
    }
    if (t < SCAN_NB) g_boff[t] = s[t] - v;
    if (t == 127) g_off[NN] = s[127];
}

__global__ void k_scan3() {
    int i = blockIdx.x * SCAN_BS + threadIdx.x;
    if (i >= NN) return;
    int o = g_off[i] + g_boff[blockIdx.x];
    g_off[i] = o;
    g_cur[i] = o;
}

__global__ void k_scatter(const int* __restrict__ src,
                          const int* __restrict__ dst) {
    int e = blockIdx.x * blockDim.x + threadIdx.x;
    if (e >= NE) return;
    int d = __ldg(&dst[e]);
    int pos = atomicAdd(&g_cur[d], 1);
    g_csr[pos] = __ldg(&src[e]);
}

__global__ void k_gather(const int* __restrict__ ids,
                         const float* __restrict__ emb) {
    int t = blockIdx.x * blockDim.x + threadIdx.x;
    if (t >= NN * 16) return;
    int row = t >> 4, q = t & 15;
    int id = ids[row] + IDOFF;
    float4 v = *(const float4*)(emb + (size_t)id * HID + q * 4);
    *(float4*)(g_h + (size_t)row * HID + q * 4) = v;
}

// Pre-split all 9 weight matrices into packed bf16 hi/lo pairs.
// word [s][kp][n] = { W[2kp][n], W[2kp+1][n] } (low half = even k).
__global__ void k_wprep(const float* __restrict__ Ws) {
    int i = blockIdx.x * blockDim.x + threadIdx.x;
    if (i >= 9 * 32 * 64) return;
    int n = i & 63, kp = (i >> 6) & 31, s = i >> 11;
    const float* W = Ws + (size_t)s * HID * HID;
    float w0 = W[(2 * kp) * HID + n];
    float w1 = W[(2 * kp + 1) * HID + n];
    __nv_bfloat16 h0 = __float2bfloat16_rn(w0);
    __nv_bfloat16 h1 = __float2bfloat16_rn(w1);
    __nv_bfloat16 l0 = __float2bfloat16_rn(w0 - __bfloat162float(h0));
    __nv_bfloat16 l1 = __float2bfloat16_rn(w1 - __bfloat162float(h1));
    g_whi2[s * 2048 + kp * 64 + n] = pack_bf2(h0, h1);
    g_wlo2[s * 2048 + kp * 64 + n] = pack_bf2(l0, l1);
}

// x[n] = (1+eps[l]) * h[n] + sum_{s in in-nbrs(n)} h[s]   (warp per node)
__global__ __launch_bounds__(256)
void k_agg(const float* __restrict__ eps, int l) {
    int wid = (blockIdx.x * blockDim.x + threadIdx.x) >> 5;
    if (wid >= NN) return;
    int lane = threadIdx.x & 31;
    int beg = __ldg(&g_off[wid]);
    int end = __ldg(&g_off[wid + 1]);
    float2 a0 = make_float2(0.f, 0.f);
    float2 a1 = make_float2(0.f, 0.f);
    int j = beg;
    for (; j + 1 < end; j += 2) {
        int s0 = __ldg(&g_csr[j]);
        int s1 = __ldg(&g_csr[j + 1]);
        float2 v0 = __ldg((const float2*)(g_h + (size_t)s0 * HID + lane * 2));
        float2 v1 = __ldg((const float2*)(g_h + (size_t)s1 * HID + lane * 2));
        a0.x += v0.x; a0.y += v0.y;
        a1.x += v1.x; a1.y += v1.y;
    }
    if (j < end) {
        int s0 = __ldg(&g_csr[j]);
        float2 v0 = __ldg((const float2*)(g_h + (size_t)s0 * HID + lane * 2));
        a0.x += v0.x; a0.y += v0.y;
    }
    float se = 1.0f + __ldg(&eps[l]);
    float2 hv = *(const float2*)(g_h + (size_t)wid * HID + lane * 2);
    float2 o = make_float2(se * hv.x + a0.x + a1.x, se * hv.y + a0.y + a1.y);
    *(float2*)(g_x + (size_t)wid * HID + lane * 2) = o;
}

// Fused 3x (Linear 64x64 + ReLU), 3xBF16 split mma (m16n8k16), BN stats.
// X fp32 in smem stride 72 (conflict-free float2 A loads: (4g+tg) mod 16
// bijection per half-warp). W packed bf16 pairs, row stride 72 words:
// (8tg+8n+g) mod 32 bijection -> conflict-free B loads.
#define MROWS 128
#define XS 72
#define NW 72
#define MLP_SMEM ((MROWS * XS + 2 * 32 * NW + HID + 2 * HID) * 4)

__global__ __launch_bounds__(256, 2)
void k_mlp(const float* __restrict__ ball, int l) {
    extern __shared__ float sm[];
    float* Xbuf = sm;
    unsigned* Whi = (unsigned*)(sm + MROWS * XS);
    unsigned* Wlo = Whi + 32 * NW;
    float* Bsm = (float*)(Wlo + 32 * NW);
    float* bstat = Bsm + HID;

    const int t = threadIdx.x;
    const int warp = t >> 5, lane = t & 31;
    const int g = lane >> 2, tg = lane & 3;
    const int row0 = blockIdx.x * MROWS;
    const int wrow = warp * 16;

    if (t < 2 * HID) bstat[t] = 0.f;

    for (int i = t; i < MROWS * 16; i += 256) {
        int r = i >> 4, q = i & 15;
        float4 v = make_float4(0.f, 0.f, 0.f, 0.f);
        int gr = row0 + r;
        if (gr < NN) v = *(const float4*)(g_x + (size_t)gr * HID + q * 4);
        float* p = Xbuf + r * XS + q * 4;
        p[0] = v.x; p[1] = v.y; p[2] = v.z; p[3] = v.w;
    }

    for (int m = 0; m < 3; m++) {
        __syncthreads();
        int stage = l * 3 + m;
        // copy pre-split packed weights into smem (coalesced uint4)
        for (int i = t; i < 512; i += 256) {
            int j = i << 2;
            int kp = j >> 6, n = j & 63;
            *(uint4*)(Whi + kp * NW + n) = *(const uint4*)(g_whi2 + stage * 2048 + j);
            *(uint4*)(Wlo + kp * NW + n) = *(const uint4*)(g_wlo2 + stage * 2048 + j);
        }
        if (t < HID) Bsm[t] = ball[stage * HID + t];
        __syncthreads();

        float acc[8][4];
        #pragma unroll
        for (int n = 0; n < 8; n++) {
            acc[n][0] = 0.f; acc[n][1] = 0.f; acc[n][2] = 0.f; acc[n][3] = 0.f;
        }

        #pragma unroll
        for (int c = 0; c < 4; c++) {
            int k0 = c * 16;
            float2 x00 = *(const float2*)(Xbuf + (wrow + g) * XS + k0 + 2 * tg);
            float2 x10 = *(const float2*)(Xbuf + (wrow + g + 8) * XS + k0 + 2 * tg);
            float2 x08 = *(const float2*)(Xbuf + (wrow + g) * XS + k0 + 2 * tg + 8);
            float2 x18 = *(const float2*)(Xbuf + (wrow + g + 8) * XS + k0 + 2 * tg + 8);
            unsigned a0h, a0l, a1h, a1l, a2h, a2l, a3h, a3l;
            bfsplit2(x00, a0h, a0l);   // (row g,   k 2tg..2tg+1)
            bfsplit2(x10, a1h, a1l);   // (row g+8, k 2tg..2tg+1)
            bfsplit2(x08, a2h, a2l);   // (row g,   k 2tg+8..2tg+9)
            bfsplit2(x18, a3h, a3l);   // (row g+8, k 2tg+8..2tg+9)
            #pragma unroll
            for (int n = 0; n < 8; n++) {
                unsigned b0h = Whi[(c * 8 + tg) * NW + n * 8 + g];
                unsigned b1h = Whi[(c * 8 + tg + 4) * NW + n * 8 + g];
                unsigned b0l = Wlo[(c * 8 + tg) * NW + n * 8 + g];
                unsigned b1l = Wlo[(c * 8 + tg + 4) * NW + n * 8 + g];
                mma16(acc[n], a0h, a1h, a2h, a3h, b0l, b1l);  // Ahi*Blo
                mma16(acc[n], a0l, a1l, a2l, a3l, b0h, b1h);  // Alo*Bhi
                mma16(acc[n], a0h, a1h, a2h, a3h, b0h, b1h);  // Ahi*Bhi
            }
        }

        if (m < 2) {
            #pragma unroll
            for (int n = 0; n < 8; n++) {
                int c = n * 8 + 2 * tg;
                float b0f = Bsm[c], b1f = Bsm[c + 1];
                float d0 = fmaxf(acc[n][0] + b0f, 0.f);
                float d1 = fmaxf(acc[n][1] + b1f, 0.f);
                float d2 = fmaxf(acc[n][2] + b0f, 0.f);
                float d3 = fmaxf(acc[n][3] + b1f, 0.f);
                float* p0 = Xbuf + (wrow + g) * XS + c;
                p0[0] = d0; p0[1] = d1;
                float* p1 = Xbuf + (wrow + g + 8) * XS + c;
                p1[0] = d2; p1[1] = d3;
            }
            __syncwarp();
        } else {
            int r0v = row0 + wrow + g;
            int r1v = r0v + 8;
            bool v0 = r0v < NN, v1 = r1v < NN;
            #pragma unroll
            for (int n = 0; n < 8; n++) {
                int c = n * 8 + 2 * tg;
                float b0f = Bsm[c], b1f = Bsm[c + 1];
                float d0 = fmaxf(acc[n][0] + b0f, 0.f);
                float d1 = fmaxf(acc[n][1] + b1f, 0.f);
                float d2 = fmaxf(acc[n][2] + b0f, 0.f);
                float d3 = fmaxf(acc[n][3] + b1f, 0.f);
                if (v0) *(float2*)(g_y + (size_t)r0v * HID + c) = make_float2(d0, d1);
                if (v1) *(float2*)(g_y + (size_t)r1v * HID + c) = make_float2(d2, d3);
                float s0 = (v0 ? d0 : 0.f) + (v1 ? d2 : 0.f);
                float s1 = (v0 ? d1 : 0.f) + (v1 ? d3 : 0.f);
                float q0 = (v0 ? d0 * d0 : 0.f) + (v1 ? d2 * d2 : 0.f);
                float q1 = (v0 ? d1 * d1 : 0.f) + (v1 ? d3 * d3 : 0.f);
                #pragma unroll
                for (int off = 4; off < 32; off <<= 1) {
                    s0 += __shfl_xor_sync(0xffffffffu, s0, off);
                    s1 += __shfl_xor_sync(0xffffffffu, s1, off);
                    q0 += __shfl_xor_sync(0xffffffffu, q0, off);
                    q1 += __shfl_xor_sync(0xffffffffu, q1, off);
                }
                if (g == 0) {
                    atomicAdd(&bstat[c], s0);
                    atomicAdd(&bstat[c + 1], s1);
                    atomicAdd(&bstat[HID + c], q0);
                    atomicAdd(&bstat[HID + c + 1], q1);
                }
            }
        }
    }
    __syncthreads();
    if (t < 2 * HID) atomicAdd(&g_stats[l * 2 * HID + t], bstat[t]);
}

// BatchNorm apply + per-graph pooling + g_h writeback (next layer input).
__global__ void k_bnpool(const int* __restrict__ graph_ids,
                         const float* __restrict__ gamma,
                         const float* __restrict__ beta, int l) {
    __shared__ int gid[256];
    int t = threadIdx.x;
    int c = t & 63, sub = t >> 6;
    int base = blockIdx.x * 256;
    int nrow_blk = NN - base; if (nrow_blk > 256) nrow_blk = 256;
    if (t < nrow_blk) gid[t] = graph_ids[base + t];
    __syncthreads();

    float sum = g_stats[l * 2 * HID + c];
    float sq = g_stats[l * 2 * HID + HID + c];
    const float invN = 1.0f / (float)NN;
    float mean = sum * invN;
    float var = sq * invN - mean * mean;
    float inv = rsqrtf(var + 1e-5f);
    float sc = __ldg(&gamma[l * HID + c]) * inv;
    float sh = __ldg(&beta[l * HID + c]) - mean * sc;

    int r0 = sub * 64;
    int nr = nrow_blk - r0; if (nr > 64) nr = 64;
    if (nr <= 0) return;

    float run = 0.f;
    int gcur = gid[r0];
    for (int r = 0; r < nr; r++) {
        int gg = gid[r0 + r];
        if (gg != gcur) {
            atomicAdd(&g_pooled[(size_t)gcur * (3 * HID) + l * HID + c], run);
            run = 0.f;
            gcur = gg;
        }
        size_t off = (size_t)(base + r0 + r) * HID + c;
        float v = g_y[off] * sc + sh;
        if (l < 2) g_h[off] = v;
        run += v;
    }
    atomicAdd(&g_pooled[(size_t)gcur * (3 * HID) + l * HID + c], run);
}

// out[g] = pooled[g] @ W_out + b_out
__global__ void k_out(const float* __restrict__ Wo,
                      const float* __restrict__ bo,
                      float* __restrict__ out) {
    __shared__ float p[3 * HID];
    int gr = blockIdx.x;
    int t = threadIdx.x;
    for (int i = t; i < 3 * HID; i += blockDim.x)
        p[i] = g_pooled[(size_t)gr * (3 * HID) + i];
    __syncthreads();
    if (t < NCLS) {
        float a = __ldg(&bo[t]);
        #pragma unroll 8
        for (int k = 0; k < 3 * HID; k++) a += p[k] * Wo[(size_t)k * NCLS + t];
        out[(size_t)gr * NCLS + t] = a;
    }
}

// ---------------- launch ----------------
extern "C" void kernel_launch(void* const* d_in, const int* in_sizes, int n_in,
                              void* d_out, int out_size) {
    const int* node_ids = (const int*)d_in[0];
    const int* edge_src = (const int*)d_in[1];
    const int* edge_dst = (const int*)d_in[2];
    const int* graph_ids = (const int*)d_in[3];
    const float* emb = (const float*)d_in[4];
    const float* Ws = (const float*)d_in[5];
    const float* bs = (const float*)d_in[6];
    const float* gamma = (const float*)d_in[7];
    const float* beta = (const float*)d_in[8];
    const float* eps = (const float*)d_in[9];
    const float* Wo = (const float*)d_in[10];
    const float* bo = (const float*)d_in[11];
    float* out = (float*)d_out;

    cudaFuncSetAttribute(k_mlp, cudaFuncAttributeMaxDynamicSharedMemorySize,
                         MLP_SMEM);

    k_zero<<<256, 256>>>();
    k_hist<<<(NE + 255) / 256, 256>>>(edge_dst);
    k_gather<<<(NN * 16 + 255) / 256, 256>>>(node_ids, emb);
    k_wprep<<<(9 * 32 * 64 + 255) / 256, 256>>>(Ws);
    k_scan1<<<SCAN_NB, SCAN_BS>>>();
    k_scan2<<<1, 128>>>();
    k_scan3<<<SCAN_NB, SCAN_BS>>>();
    k_scatter<<<(NE + 255) / 256, 256>>>(edge_src, edge_dst);

    for (int l = 0; l < 3; l++) {
        k_agg<<<(NN * 32 + 255) / 256, 256>>>(eps, l);
        k_mlp<<<(NN + MROWS - 1) / MROWS, 256, MLP_SMEM>>>(bs, l);
        k_bnpool<<<(NN + 255) / 256, 256>>>(graph_ids, gamma, beta, l);
    }

    k_out<<<NG, 128>>>(Wo, bo, out);
}